// round 1
// baseline (speedup 1.0000x reference)
#include <cuda_runtime.h>
#include <math.h>

#define H_    512
#define W_    1408
#define HW    (H_ * W_)        // 720896 = 2816 * 256
#define NPTS  640000
#define NCAM  6
#define NCH   17
#define CP    20               // padded channels -> 80B per pixel, 16B aligned

// Scratch (allocation-free rule: __device__ globals).
// 6 * 720896 * 20 floats = 330 MB, zero-initialized at module load.
// Invariant: zero at entry of every kernel_launch (loss kernel re-zeroes).
__device__ __align__(256) float g_image[(size_t)NCAM * HW * CP];
__device__ float g_num[NCAM];
__device__ float g_den[NCAM];

__device__ __forceinline__ void red_add_v4(float* addr, float a, float b, float c, float d) {
    asm volatile("red.global.add.v4.f32 [%0], {%1, %2, %3, %4};"
                 :: "l"(addr), "f"(a), "f"(b), "f"(c), "f"(d)
                 : "memory");
}

__global__ __launch_bounds__(256)
void splat_kernel(const float* __restrict__ feats,
                  const float* __restrict__ density,
                  const float* __restrict__ viewmats,
                  const float* __restrict__ Ks,
                  const float* __restrict__ xyz)
{
    int p = blockIdx.x * 256 + threadIdx.x;
    if (p >= NPTS) return;

    float X = xyz[3 * p + 0];
    float Y = xyz[3 * p + 1];
    float Z = xyz[3 * p + 2];
    float opac = density[p];

    float f[NCH];
#pragma unroll
    for (int c = 0; c < NCH; c++) f[c] = feats[(size_t)p * NCH + c];

#pragma unroll 1
    for (int cam = 0; cam < NCAM; cam++) {
        const float* V = viewmats + cam * 16;
        const float* K = Ks + cam * 9;

        float px = V[0] * X + V[1] * Y + V[2]  * Z + V[3];
        float py = V[4] * X + V[5] * Y + V[6]  * Z + V[7];
        float pz = V[8] * X + V[9] * Y + V[10] * Z + V[11];

        // reference: valid requires p.z > 0.1 (else all 9 taps contribute 0)
        if (!(pz > 0.1f)) continue;

        float z  = fmaxf(pz, 0.001f);
        float fx = K[0], cx = K[2], fy = K[4], cy = K[5];

        float u = fx * px / z + cx;
        float v = fy * py / z + cy;

        const float s2 = 0.4f * 0.4f;
        float j00 = fx / z;
        float j11 = fy / z;
        float j02 = -fx * px / (z * z);
        float j12 = -fy * py / (z * z);

        float a = s2 * (j00 * j00 + j02 * j02) + 0.3f;
        float b = s2 * (j02 * j12);
        float c = s2 * (j11 * j11 + j12 * j12) + 0.3f;
        float det = a * c - b * b;
        float ca =  c / det;
        float cb = -b / det;
        float cc =  a / det;

        float ru = rintf(u);   // matches jnp.round (half-to-even)
        float rv = rintf(v);

#pragma unroll
        for (int dx = -1; dx <= 1; dx++) {
            float pxx = ru + (float)dx;
            if (pxx < 0.0f || pxx >= (float)W_) continue;
            float ddx = pxx - u;
#pragma unroll
            for (int dy = -1; dy <= 1; dy++) {
                float pyy = rv + (float)dy;
                if (pyy < 0.0f || pyy >= (float)H_) continue;
                float ddy = pyy - v;

                float e = -0.5f * (ca * ddx * ddx + 2.0f * cb * ddx * ddy + cc * ddy * ddy);
                float w = opac * expf(e);

                int pix = (int)pyy * W_ + (int)pxx;
                float* bp = g_image + ((size_t)cam * HW + (size_t)pix) * CP;

                red_add_v4(bp + 0,  w * f[0],  w * f[1],  w * f[2],  w * f[3]);
                red_add_v4(bp + 4,  w * f[4],  w * f[5],  w * f[6],  w * f[7]);
                red_add_v4(bp + 8,  w * f[8],  w * f[9],  w * f[10], w * f[11]);
                red_add_v4(bp + 12, w * f[12], w * f[13], w * f[14], w * f[15]);
                atomicAdd(bp + 16,  w * f[16]);
            }
        }
    }
}

__global__ __launch_bounds__(256)
void loss_kernel(const int* __restrict__ gt, const float* __restrict__ cw)
{
    int cam = blockIdx.y;
    int pix = blockIdx.x * 256 + threadIdx.x;

    float nwl = 0.0f, wv = 0.0f;

    if (pix < HW) {
        float* bp = g_image + ((size_t)cam * HW + (size_t)pix) * CP;

        float l[NCH];
        float4 t;
        t = ((const float4*)bp)[0]; l[0]  = t.x; l[1]  = t.y; l[2]  = t.z; l[3]  = t.w;
        t = ((const float4*)bp)[1]; l[4]  = t.x; l[5]  = t.y; l[6]  = t.z; l[7]  = t.w;
        t = ((const float4*)bp)[2]; l[8]  = t.x; l[9]  = t.y; l[10] = t.z; l[11] = t.w;
        t = ((const float4*)bp)[3]; l[12] = t.x; l[13] = t.y; l[14] = t.z; l[15] = t.w;
        l[16] = bp[16];

        float m = l[0];
#pragma unroll
        for (int c = 1; c < NCH; c++) m = fmaxf(m, l[c]);
        float s = 0.0f;
#pragma unroll
        for (int c = 0; c < NCH; c++) s += expf(l[c] - m);
        float lse = m + logf(s);

        int g = gt[(size_t)cam * HW + (size_t)pix];   // in [0,17)
        float lg = bp[g];                              // avoid dynamic local-array index
        float w = (g != 0) ? cw[g] : 0.0f;

        nwl = w * (lse - lg);
        wv  = w;

        // restore invariant: zero the image for the next launch
        float4 z4 = make_float4(0.f, 0.f, 0.f, 0.f);
        ((float4*)bp)[0] = z4;
        ((float4*)bp)[1] = z4;
        ((float4*)bp)[2] = z4;
        ((float4*)bp)[3] = z4;
        bp[16] = 0.0f;
    }

    // block reduction
#pragma unroll
    for (int o = 16; o > 0; o >>= 1) {
        nwl += __shfl_down_sync(0xffffffffu, nwl, o);
        wv  += __shfl_down_sync(0xffffffffu, wv,  o);
    }
    __shared__ float sh[16];
    int lane = threadIdx.x & 31;
    int wid  = threadIdx.x >> 5;
    if (lane == 0) { sh[wid] = nwl; sh[8 + wid] = wv; }
    __syncthreads();
    if (threadIdx.x == 0) {
        float an = 0.0f, ad = 0.0f;
#pragma unroll
        for (int i = 0; i < 8; i++) { an += sh[i]; ad += sh[8 + i]; }
        atomicAdd(&g_num[cam], an);
        atomicAdd(&g_den[cam], ad);
    }
}

__global__ void finalize_kernel(float* out)
{
    if (threadIdx.x == 0 && blockIdx.x == 0) {
        float L = 0.0f;
#pragma unroll
        for (int cam = 0; cam < NCAM; cam++) {
            L += g_num[cam] / fmaxf(g_den[cam], 1e-8f);
            g_num[cam] = 0.0f;   // reset accumulators for next replay
            g_den[cam] = 0.0f;
        }
        out[0] = L / (float)NCAM;
    }
}

extern "C" void kernel_launch(void* const* d_in, const int* in_sizes, int n_in,
                              void* d_out, int out_size)
{
    const float* voxel_feats = (const float*)d_in[0];
    const float* density     = (const float*)d_in[1];
    const float* viewmats    = (const float*)d_in[2];
    const float* Ks          = (const float*)d_in[3];
    const int*   gt_sem      = (const int*)d_in[4];
    const float* pc_xyz      = (const float*)d_in[5];
    const float* cls_w       = (const float*)d_in[6];

    splat_kernel<<<(NPTS + 255) / 256, 256>>>(voxel_feats, density, viewmats, Ks, pc_xyz);

    dim3 grid(HW / 256, NCAM);
    loss_kernel<<<grid, 256>>>(gt_sem, cls_w);

    finalize_kernel<<<1, 32>>>((float*)d_out);
}

// round 2
// speedup vs baseline: 1.0885x; 1.0885x over previous
#include <cuda_runtime.h>
#include <math.h>

#define H_    512
#define W_    1408
#define HW    (H_ * W_)        // 720896 = 2816 * 256
#define NPTS  640000
#define NCAM  6
#define NCH   17
#define CP    20               // padded channels -> 80B per pixel, 16B aligned

// Scratch (allocation-free rule: __device__ globals).
// ONE camera image buffer, reused for all 6 cameras: 720896*20*4B = 57.7MB.
// Fits in L2 (126MB) -> atomics stay L2-resident.
// Invariant: zero at entry of every kernel_launch AND before each splat(c)
// (loss(c) re-zeroes the whole buffer right after reading it).
__device__ __align__(256) float g_image[(size_t)HW * CP];
__device__ float g_num[NCAM];
__device__ float g_den[NCAM];

__device__ __forceinline__ void red_add_v4(float* addr, float a, float b, float c, float d) {
    asm volatile("red.global.add.v4.f32 [%0], {%1, %2, %3, %4};"
                 :: "l"(addr), "f"(a), "f"(b), "f"(c), "f"(d)
                 : "memory");
}

__global__ __launch_bounds__(256)
void splat_kernel(int cam,
                  const float* __restrict__ feats,
                  const float* __restrict__ density,
                  const float* __restrict__ viewmats,
                  const float* __restrict__ Ks,
                  const float* __restrict__ xyz)
{
    int p = blockIdx.x * 256 + threadIdx.x;
    if (p >= NPTS) return;

    float X = xyz[3 * p + 0];
    float Y = xyz[3 * p + 1];
    float Z = xyz[3 * p + 2];

    const float* V = viewmats + cam * 16;
    const float* K = Ks + cam * 9;

    float px = V[0] * X + V[1] * Y + V[2]  * Z + V[3];
    float py = V[4] * X + V[5] * Y + V[6]  * Z + V[7];
    float pz = V[8] * X + V[9] * Y + V[10] * Z + V[11];

    // reference: valid requires p.z > 0.1 (else all 9 taps contribute 0)
    if (!(pz > 0.1f)) return;

    float z  = fmaxf(pz, 0.001f);
    float fx = K[0], cx = K[2], fy = K[4], cy = K[5];

    float u = fx * px / z + cx;
    float v = fy * py / z + cy;

    const float s2 = 0.4f * 0.4f;
    float j00 = fx / z;
    float j11 = fy / z;
    float j02 = -fx * px / (z * z);
    float j12 = -fy * py / (z * z);

    float a = s2 * (j00 * j00 + j02 * j02) + 0.3f;
    float b = s2 * (j02 * j12);
    float c = s2 * (j11 * j11 + j12 * j12) + 0.3f;
    float det = a * c - b * b;
    float ca =  c / det;
    float cb = -b / det;
    float cc =  a / det;

    float ru = rintf(u);   // matches jnp.round (half-to-even)
    float rv = rintf(v);

    // quick full-footprint reject (all 9 taps out of image)
    if (ru < -1.0f || ru > (float)W_ || rv < -1.0f || rv > (float)H_) return;

    float opac = density[p];
    float f[NCH];
#pragma unroll
    for (int ch = 0; ch < NCH; ch++) f[ch] = feats[(size_t)p * NCH + ch];

#pragma unroll
    for (int dx = -1; dx <= 1; dx++) {
        float pxx = ru + (float)dx;
        if (pxx < 0.0f || pxx >= (float)W_) continue;
        float ddx = pxx - u;
#pragma unroll
        for (int dy = -1; dy <= 1; dy++) {
            float pyy = rv + (float)dy;
            if (pyy < 0.0f || pyy >= (float)H_) continue;
            float ddy = pyy - v;

            float e = -0.5f * (ca * ddx * ddx + 2.0f * cb * ddx * ddy + cc * ddy * ddy);
            float w = opac * __expf(e);

            int pix = (int)pyy * W_ + (int)pxx;
            float* bp = g_image + (size_t)pix * CP;

            red_add_v4(bp + 0,  w * f[0],  w * f[1],  w * f[2],  w * f[3]);
            red_add_v4(bp + 4,  w * f[4],  w * f[5],  w * f[6],  w * f[7]);
            red_add_v4(bp + 8,  w * f[8],  w * f[9],  w * f[10], w * f[11]);
            red_add_v4(bp + 12, w * f[12], w * f[13], w * f[14], w * f[15]);
            atomicAdd(bp + 16,  w * f[16]);
        }
    }
}

__global__ __launch_bounds__(256)
void loss_kernel(int cam, const int* __restrict__ gt, const float* __restrict__ cw)
{
    int pix = blockIdx.x * 256 + threadIdx.x;

    float nwl = 0.0f, wv = 0.0f;

    {
        float* bp = g_image + (size_t)pix * CP;

        float l[NCH];
        float4 t;
        t = ((const float4*)bp)[0]; l[0]  = t.x; l[1]  = t.y; l[2]  = t.z; l[3]  = t.w;
        t = ((const float4*)bp)[1]; l[4]  = t.x; l[5]  = t.y; l[6]  = t.z; l[7]  = t.w;
        t = ((const float4*)bp)[2]; l[8]  = t.x; l[9]  = t.y; l[10] = t.z; l[11] = t.w;
        t = ((const float4*)bp)[3]; l[12] = t.x; l[13] = t.y; l[14] = t.z; l[15] = t.w;
        l[16] = bp[16];

        float m = l[0];
#pragma unroll
        for (int ch = 1; ch < NCH; ch++) m = fmaxf(m, l[ch]);
        float s = 0.0f;
#pragma unroll
        for (int ch = 0; ch < NCH; ch++) s += __expf(l[ch] - m);
        float lse = m + __logf(s);

        int g = gt[(size_t)cam * HW + (size_t)pix];   // in [0,17)
        float lg = bp[g];                              // avoid dynamic local-array index
        float w = (g != 0) ? cw[g] : 0.0f;

        nwl = w * (lse - lg);
        wv  = w;

        // restore invariant: zero the image before the next camera's splat
        float4 z4 = make_float4(0.f, 0.f, 0.f, 0.f);
        ((float4*)bp)[0] = z4;
        ((float4*)bp)[1] = z4;
        ((float4*)bp)[2] = z4;
        ((float4*)bp)[3] = z4;
        ((float4*)bp)[4] = z4;   // CP=20: covers ch 16..19
    }

    // block reduction
#pragma unroll
    for (int o = 16; o > 0; o >>= 1) {
        nwl += __shfl_down_sync(0xffffffffu, nwl, o);
        wv  += __shfl_down_sync(0xffffffffu, wv,  o);
    }
    __shared__ float sh[16];
    int lane = threadIdx.x & 31;
    int wid  = threadIdx.x >> 5;
    if (lane == 0) { sh[wid] = nwl; sh[8 + wid] = wv; }
    __syncthreads();
    if (threadIdx.x == 0) {
        float an = 0.0f, ad = 0.0f;
#pragma unroll
        for (int i = 0; i < 8; i++) { an += sh[i]; ad += sh[8 + i]; }
        atomicAdd(&g_num[cam], an);
        atomicAdd(&g_den[cam], ad);
    }
}

__global__ void finalize_kernel(float* out)
{
    if (threadIdx.x == 0 && blockIdx.x == 0) {
        float L = 0.0f;
#pragma unroll
        for (int cam = 0; cam < NCAM; cam++) {
            L += g_num[cam] / fmaxf(g_den[cam], 1e-8f);
            g_num[cam] = 0.0f;   // reset accumulators for next replay
            g_den[cam] = 0.0f;
        }
        out[0] = L / (float)NCAM;
    }
}

extern "C" void kernel_launch(void* const* d_in, const int* in_sizes, int n_in,
                              void* d_out, int out_size)
{
    const float* voxel_feats = (const float*)d_in[0];
    const float* density     = (const float*)d_in[1];
    const float* viewmats    = (const float*)d_in[2];
    const float* Ks          = (const float*)d_in[3];
    const int*   gt_sem      = (const int*)d_in[4];
    const float* pc_xyz      = (const float*)d_in[5];
    const float* cls_w       = (const float*)d_in[6];

    for (int cam = 0; cam < NCAM; cam++) {
        splat_kernel<<<(NPTS + 255) / 256, 256>>>(cam, voxel_feats, density,
                                                  viewmats, Ks, pc_xyz);
        loss_kernel<<<HW / 256, 256>>>(cam, gt_sem, cls_w);
    }
    finalize_kernel<<<1, 32>>>((float*)d_out);
}

// round 5
// speedup vs baseline: 1.6426x; 1.5091x over previous
#include <cuda_runtime.h>
#include <cuda_fp16.h>
#include <math.h>

#define H_    512
#define W_    1408
#define HW    (H_ * W_)        // 720896 = 2816 * 256
#define NPTS  640000
#define NCAM  6
#define NCH   17
#define CPH   24               // padded channels in halves -> 48B per pixel, 16B aligned

// Scratch (allocation-free rule: __device__ globals).
// ONE camera image buffer in fp16, reused for all 6 cameras:
// 720896 * 24 * 2B = 34.6MB -> fully L2-resident with room for streamed inputs.
// Invariant: zero at entry of every kernel_launch AND before each splat(c)
// (loss(c) re-zeroes the whole buffer right after reading it).
__device__ __align__(256) __half g_image[(size_t)HW * CPH];
__device__ float g_num[NCAM];
__device__ float g_den[NCAM];

__device__ __forceinline__ unsigned h2_bits(__half2 h) {
    unsigned u;
    memcpy(&u, &h, 4);
    return u;
}

__device__ __forceinline__ void red_add_v4_h2(__half* addr, unsigned a, unsigned b,
                                              unsigned c, unsigned d) {
    asm volatile("red.global.add.noftz.v4.f16x2 [%0], {%1, %2, %3, %4};"
                 :: "l"(addr), "r"(a), "r"(b), "r"(c), "r"(d)
                 : "memory");
}
__device__ __forceinline__ void red_add_h2(__half* addr, unsigned a) {
    asm volatile("red.global.add.noftz.f16x2 [%0], %1;"
                 :: "l"(addr), "r"(a)
                 : "memory");
}

__global__ __launch_bounds__(256)
void splat_kernel(int cam,
                  const float* __restrict__ feats,
                  const float* __restrict__ density,
                  const float* __restrict__ viewmats,
                  const float* __restrict__ Ks,
                  const float* __restrict__ xyz)
{
    int p = blockIdx.x * 256 + threadIdx.x;
    if (p >= NPTS) return;

    float X = xyz[3 * p + 0];
    float Y = xyz[3 * p + 1];
    float Z = xyz[3 * p + 2];

    const float* V = viewmats + cam * 16;
    const float* K = Ks + cam * 9;

    float px = V[0] * X + V[1] * Y + V[2]  * Z + V[3];
    float py = V[4] * X + V[5] * Y + V[6]  * Z + V[7];
    float pz = V[8] * X + V[9] * Y + V[10] * Z + V[11];

    // reference: valid requires p.z > 0.1 (else all 9 taps contribute 0)
    if (!(pz > 0.1f)) return;

    float z  = fmaxf(pz, 0.001f);
    float fx = K[0], cx = K[2], fy = K[4], cy = K[5];

    float u = fx * px / z + cx;
    float v = fy * py / z + cy;

    const float s2 = 0.4f * 0.4f;
    float j00 = fx / z;
    float j11 = fy / z;
    float j02 = -fx * px / (z * z);
    float j12 = -fy * py / (z * z);

    float a = s2 * (j00 * j00 + j02 * j02) + 0.3f;
    float b = s2 * (j02 * j12);
    float c = s2 * (j11 * j11 + j12 * j12) + 0.3f;
    float det = a * c - b * b;
    float ca =  c / det;
    float cb = -b / det;
    float cc =  a / det;

    float ru = rintf(u);   // matches jnp.round (half-to-even)
    float rv = rintf(v);

    // quick full-footprint reject (all 9 taps out of image)
    if (ru < -1.0f || ru > (float)W_ || rv < -1.0f || rv > (float)H_) return;

    float opac = density[p];

    // Pack the 17-ch feature vector into 9 half2 registers (pad with 0).
    __half2 fh[9];
    {
        float f[NCH];
#pragma unroll
        for (int ch = 0; ch < NCH; ch++) f[ch] = feats[(size_t)p * NCH + ch];
#pragma unroll
        for (int i = 0; i < 8; i++) fh[i] = __floats2half2_rn(f[2 * i], f[2 * i + 1]);
        fh[8] = __floats2half2_rn(f[16], 0.0f);
    }

#pragma unroll
    for (int dx = -1; dx <= 1; dx++) {
        float pxx = ru + (float)dx;
        if (pxx < 0.0f || pxx >= (float)W_) continue;
        float ddx = pxx - u;
#pragma unroll
        for (int dy = -1; dy <= 1; dy++) {
            float pyy = rv + (float)dy;
            if (pyy < 0.0f || pyy >= (float)H_) continue;
            float ddy = pyy - v;

            float e = -0.5f * (ca * ddx * ddx + 2.0f * cb * ddx * ddy + cc * ddy * ddy);
            float w = opac * __expf(e);
            __half2 wh = __float2half2_rn(w);

            int pix = (int)pyy * W_ + (int)pxx;
            __half* bp = g_image + (size_t)pix * CPH;

            __half2 m0 = __hmul2(wh, fh[0]);
            __half2 m1 = __hmul2(wh, fh[1]);
            __half2 m2 = __hmul2(wh, fh[2]);
            __half2 m3 = __hmul2(wh, fh[3]);
            __half2 m4 = __hmul2(wh, fh[4]);
            __half2 m5 = __hmul2(wh, fh[5]);
            __half2 m6 = __hmul2(wh, fh[6]);
            __half2 m7 = __hmul2(wh, fh[7]);
            __half2 m8 = __hmul2(wh, fh[8]);

            red_add_v4_h2(bp + 0, h2_bits(m0), h2_bits(m1), h2_bits(m2), h2_bits(m3));
            red_add_v4_h2(bp + 8, h2_bits(m4), h2_bits(m5), h2_bits(m6), h2_bits(m7));
            red_add_h2(bp + 16, h2_bits(m8));
        }
    }
}

__global__ __launch_bounds__(256)
void loss_kernel(int cam, const int* __restrict__ gt, const float* __restrict__ cw)
{
    int pix = blockIdx.x * 256 + threadIdx.x;

    float nwl = 0.0f, wv = 0.0f;

    {
        __half* bp = g_image + (size_t)pix * CPH;

        // load 40B of useful payload (17 ch) via 16B chunks
        uint4 q0 = ((const uint4*)bp)[0];   // halves 0..7
        uint4 q1 = ((const uint4*)bp)[1];   // halves 8..15
        unsigned q2 = ((const unsigned*)bp)[8];  // halves 16,17

        float l[NCH];
        {
            float2 t;
            t = __half22float2(*(__half2*)&q0.x); l[0] = t.x;  l[1] = t.y;
            t = __half22float2(*(__half2*)&q0.y); l[2] = t.x;  l[3] = t.y;
            t = __half22float2(*(__half2*)&q0.z); l[4] = t.x;  l[5] = t.y;
            t = __half22float2(*(__half2*)&q0.w); l[6] = t.x;  l[7] = t.y;
            t = __half22float2(*(__half2*)&q1.x); l[8] = t.x;  l[9] = t.y;
            t = __half22float2(*(__half2*)&q1.y); l[10] = t.x; l[11] = t.y;
            t = __half22float2(*(__half2*)&q1.z); l[12] = t.x; l[13] = t.y;
            t = __half22float2(*(__half2*)&q1.w); l[14] = t.x; l[15] = t.y;
            t = __half22float2(*(__half2*)&q2);   l[16] = t.x;
        }

        float m = l[0];
#pragma unroll
        for (int ch = 1; ch < NCH; ch++) m = fmaxf(m, l[ch]);
        float s = 0.0f;
#pragma unroll
        for (int ch = 0; ch < NCH; ch++) s += __expf(l[ch] - m);
        float lse = m + __logf(s);

        int g = gt[(size_t)cam * HW + (size_t)pix];   // in [0,17)
        float lg = __half2float(bp[g]);                // dynamic channel read
        float w = (g != 0) ? cw[g] : 0.0f;

        nwl = w * (lse - lg);
        wv  = w;

        // restore invariant: zero the image before the next camera's splat
        uint4 z4 = make_uint4(0u, 0u, 0u, 0u);
        ((uint4*)bp)[0] = z4;
        ((uint4*)bp)[1] = z4;
        ((uint4*)bp)[2] = z4;   // halves 16..23
    }

    // block reduction
#pragma unroll
    for (int o = 16; o > 0; o >>= 1) {
        nwl += __shfl_down_sync(0xffffffffu, nwl, o);
        wv  += __shfl_down_sync(0xffffffffu, wv,  o);
    }
    __shared__ float sh[16];
    int lane = threadIdx.x & 31;
    int wid  = threadIdx.x >> 5;
    if (lane == 0) { sh[wid] = nwl; sh[8 + wid] = wv; }
    __syncthreads();
    if (threadIdx.x == 0) {
        float an = 0.0f, ad = 0.0f;
#pragma unroll
        for (int i = 0; i < 8; i++) { an += sh[i]; ad += sh[8 + i]; }
        atomicAdd(&g_num[cam], an);
        atomicAdd(&g_den[cam], ad);
    }
}

__global__ void finalize_kernel(float* out)
{
    if (threadIdx.x == 0 && blockIdx.x == 0) {
        float L = 0.0f;
#pragma unroll
        for (int cam = 0; cam < NCAM; cam++) {
            L += g_num[cam] / fmaxf(g_den[cam], 1e-8f);
            g_num[cam] = 0.0f;   // reset accumulators for next replay
            g_den[cam] = 0.0f;
        }
        out[0] = L / (float)NCAM;
    }
}

extern "C" void kernel_launch(void* const* d_in, const int* in_sizes, int n_in,
                              void* d_out, int out_size)
{
    const float* voxel_feats = (const float*)d_in[0];
    const float* density     = (const float*)d_in[1];
    const float* viewmats    = (const float*)d_in[2];
    const float* Ks          = (const float*)d_in[3];
    const int*   gt_sem      = (const int*)d_in[4];
    const float* pc_xyz      = (const float*)d_in[5];
    const float* cls_w       = (const float*)d_in[6];

    for (int cam = 0; cam < NCAM; cam++) {
        splat_kernel<<<(NPTS + 255) / 256, 256>>>(cam, voxel_feats, density,
                                                  viewmats, Ks, pc_xyz);
        loss_kernel<<<HW / 256, 256>>>(cam, gt_sem, cls_w);
    }
    finalize_kernel<<<1, 32>>>((float*)d_out);
}

// round 6
// speedup vs baseline: 1.7201x; 1.0472x over previous
#include <cuda_runtime.h>
#include <cuda_fp16.h>
#include <math.h>
#include <string.h>

#define H_    512
#define W_    1408
#define HW    (H_ * W_)        // 720896 = 704 * 1024
#define NPTS  640000
#define NCAM  6
#define NCH   17
#define CPH   24               // padded channels in halves -> 48B per pixel, 16B aligned

// Scratch (allocation-free rule: __device__ globals).
// TWO ping-pong fp16 image buffers (34.6MB each, 69MB total -> L2-resident).
// Invariant: both zero at entry of every kernel_launch; loss(c) re-zeroes the
// buffer it reads, and the next user of that buffer is 2 kernels downstream.
__device__ __align__(256) __half g_image[2][(size_t)HW * CPH];
__device__ float g_num[NCAM];
__device__ float g_den[NCAM];

__device__ __forceinline__ unsigned h2_bits(__half2 h) {
    unsigned u;
    memcpy(&u, &h, 4);
    return u;
}

__device__ __forceinline__ void red_add_v4_h2(__half* addr, unsigned a, unsigned b,
                                              unsigned c, unsigned d) {
    asm volatile("red.global.add.noftz.v4.f16x2 [%0], {%1, %2, %3, %4};"
                 :: "l"(addr), "r"(a), "r"(b), "r"(c), "r"(d)
                 : "memory");
}
__device__ __forceinline__ void red_add_h2(__half* addr, unsigned a) {
    asm volatile("red.global.add.noftz.f16x2 [%0], %1;"
                 :: "l"(addr), "r"(a)
                 : "memory");
}

__global__ __launch_bounds__(256)
void splat_kernel(int cam, int buf,
                  const float* __restrict__ feats,
                  const float* __restrict__ density,
                  const float* __restrict__ viewmats,
                  const float* __restrict__ Ks,
                  const float* __restrict__ xyz)
{
    int p = blockIdx.x * 256 + threadIdx.x;
    if (p >= NPTS) return;

    float X = __ldcs(xyz + 3 * p + 0);
    float Y = __ldcs(xyz + 3 * p + 1);
    float Z = __ldcs(xyz + 3 * p + 2);

    const float* V = viewmats + cam * 16;
    const float* K = Ks + cam * 9;

    float px = V[0] * X + V[1] * Y + V[2]  * Z + V[3];
    float py = V[4] * X + V[5] * Y + V[6]  * Z + V[7];
    float pz = V[8] * X + V[9] * Y + V[10] * Z + V[11];

    // reference: valid requires p.z > 0.1 (else all 9 taps contribute 0)
    if (!(pz > 0.1f)) return;

    float z  = fmaxf(pz, 0.001f);
    float fx = K[0], cx = K[2], fy = K[4], cy = K[5];

    float u = fx * px / z + cx;
    float v = fy * py / z + cy;

    const float s2 = 0.4f * 0.4f;
    float j00 = fx / z;
    float j11 = fy / z;
    float j02 = -fx * px / (z * z);
    float j12 = -fy * py / (z * z);

    float a = s2 * (j00 * j00 + j02 * j02) + 0.3f;
    float b = s2 * (j02 * j12);
    float c = s2 * (j11 * j11 + j12 * j12) + 0.3f;
    float det = a * c - b * b;
    float ca =  c / det;
    float cb = -b / det;
    float cc =  a / det;

    float ru = rintf(u);   // matches jnp.round (half-to-even)
    float rv = rintf(v);

    // quick full-footprint reject (all 9 taps out of image)
    if (ru < -1.0f || ru > (float)W_ || rv < -1.0f || rv > (float)H_) return;

    float opac = __ldcs(density + p);

    // Pack the 17-ch feature vector into 9 half2 registers (pad with 0).
    __half2 fh[9];
    {
        float f[NCH];
#pragma unroll
        for (int ch = 0; ch < NCH; ch++) f[ch] = __ldcs(feats + (size_t)p * NCH + ch);
#pragma unroll
        for (int i = 0; i < 8; i++) fh[i] = __floats2half2_rn(f[2 * i], f[2 * i + 1]);
        fh[8] = __floats2half2_rn(f[16], 0.0f);
    }

    __half* img = g_image[buf];

#pragma unroll
    for (int dx = -1; dx <= 1; dx++) {
        float pxx = ru + (float)dx;
        if (pxx < 0.0f || pxx >= (float)W_) continue;
        float ddx = pxx - u;
#pragma unroll
        for (int dy = -1; dy <= 1; dy++) {
            float pyy = rv + (float)dy;
            if (pyy < 0.0f || pyy >= (float)H_) continue;
            float ddy = pyy - v;

            float e = -0.5f * (ca * ddx * ddx + 2.0f * cb * ddx * ddy + cc * ddy * ddy);
            float w = opac * __expf(e);
            __half2 wh = __float2half2_rn(w);

            int pix = (int)pyy * W_ + (int)pxx;
            __half* bp = img + (size_t)pix * CPH;

            __half2 m0 = __hmul2(wh, fh[0]);
            __half2 m1 = __hmul2(wh, fh[1]);
            __half2 m2 = __hmul2(wh, fh[2]);
            __half2 m3 = __hmul2(wh, fh[3]);
            __half2 m4 = __hmul2(wh, fh[4]);
            __half2 m5 = __hmul2(wh, fh[5]);
            __half2 m6 = __hmul2(wh, fh[6]);
            __half2 m7 = __hmul2(wh, fh[7]);
            __half2 m8 = __hmul2(wh, fh[8]);

            red_add_v4_h2(bp + 0, h2_bits(m0), h2_bits(m1), h2_bits(m2), h2_bits(m3));
            red_add_v4_h2(bp + 8, h2_bits(m4), h2_bits(m5), h2_bits(m6), h2_bits(m7));
            red_add_h2(bp + 16, h2_bits(m8));
        }
    }
}

// Single-wave loss: 704 blocks x 256 threads x 4 pixels.
// Triggers PDL completion at entry so the next splat (other buffer) overlaps.
__global__ __launch_bounds__(256)
void loss_kernel(int cam, int buf, const int* __restrict__ gt, const float* __restrict__ cw)
{
#if __CUDA_ARCH__ >= 900
    cudaTriggerProgrammaticLaunchCompletion();
#endif

    float nwl = 0.0f, wv = 0.0f;
    __half* img = g_image[buf];

#pragma unroll
    for (int j = 0; j < 4; j++) {
        int pix = blockIdx.x * 1024 + j * 256 + threadIdx.x;
        __half* bp = img + (size_t)pix * CPH;

        uint4 q0 = ((const uint4*)bp)[0];        // halves 0..7
        uint4 q1 = ((const uint4*)bp)[1];        // halves 8..15
        unsigned q2 = ((const unsigned*)bp)[8];  // halves 16,17

        float l[NCH];
        {
            float2 t;
            t = __half22float2(*(__half2*)&q0.x); l[0] = t.x;  l[1] = t.y;
            t = __half22float2(*(__half2*)&q0.y); l[2] = t.x;  l[3] = t.y;
            t = __half22float2(*(__half2*)&q0.z); l[4] = t.x;  l[5] = t.y;
            t = __half22float2(*(__half2*)&q0.w); l[6] = t.x;  l[7] = t.y;
            t = __half22float2(*(__half2*)&q1.x); l[8] = t.x;  l[9] = t.y;
            t = __half22float2(*(__half2*)&q1.y); l[10] = t.x; l[11] = t.y;
            t = __half22float2(*(__half2*)&q1.z); l[12] = t.x; l[13] = t.y;
            t = __half22float2(*(__half2*)&q1.w); l[14] = t.x; l[15] = t.y;
            t = __half22float2(*(__half2*)&q2);   l[16] = t.x;
        }

        float m = l[0];
#pragma unroll
        for (int ch = 1; ch < NCH; ch++) m = fmaxf(m, l[ch]);
        float s = 0.0f;
#pragma unroll
        for (int ch = 0; ch < NCH; ch++) s += __expf(l[ch] - m);
        float lse = m + __logf(s);

        int g = __ldcs(gt + (size_t)cam * HW + pix);  // in [0,17)
        float lg = __half2float(bp[g]);               // dynamic channel read
        float w = (g != 0) ? cw[g] : 0.0f;

        nwl += w * (lse - lg);
        wv  += w;

        // restore invariant: zero the image before this buffer's next splat
        uint4 z4 = make_uint4(0u, 0u, 0u, 0u);
        ((uint4*)bp)[0] = z4;
        ((uint4*)bp)[1] = z4;
        ((uint4*)bp)[2] = z4;   // halves 16..23
    }

    // block reduction
#pragma unroll
    for (int o = 16; o > 0; o >>= 1) {
        nwl += __shfl_down_sync(0xffffffffu, nwl, o);
        wv  += __shfl_down_sync(0xffffffffu, wv,  o);
    }
    __shared__ float sh[16];
    int lane = threadIdx.x & 31;
    int wid  = threadIdx.x >> 5;
    if (lane == 0) { sh[wid] = nwl; sh[8 + wid] = wv; }
    __syncthreads();
    if (threadIdx.x == 0) {
        float an = 0.0f, ad = 0.0f;
#pragma unroll
        for (int i = 0; i < 8; i++) { an += sh[i]; ad += sh[8 + i]; }
        atomicAdd(&g_num[cam], an);
        atomicAdd(&g_den[cam], ad);
    }
}

__global__ void finalize_kernel(float* out)
{
    if (threadIdx.x == 0 && blockIdx.x == 0) {
        float L = 0.0f;
#pragma unroll
        for (int cam = 0; cam < NCAM; cam++) {
            L += g_num[cam] / fmaxf(g_den[cam], 1e-8f);
            g_num[cam] = 0.0f;   // reset accumulators for next replay
            g_den[cam] = 0.0f;
        }
        out[0] = L / (float)NCAM;
    }
}

extern "C" void kernel_launch(void* const* d_in, const int* in_sizes, int n_in,
                              void* d_out, int out_size)
{
    const float* voxel_feats = (const float*)d_in[0];
    const float* density     = (const float*)d_in[1];
    const float* viewmats    = (const float*)d_in[2];
    const float* Ks          = (const float*)d_in[3];
    const int*   gt_sem      = (const int*)d_in[4];
    const float* pc_xyz      = (const float*)d_in[5];
    const float* cls_w       = (const float*)d_in[6];

    for (int cam = 0; cam < NCAM; cam++) {
        int buf = cam & 1;

        // splat with PDL: may start while the previous loss (other buffer) runs
        cudaLaunchConfig_t cfg = {};
        cfg.gridDim  = dim3((NPTS + 255) / 256);
        cfg.blockDim = dim3(256);
        cfg.stream   = 0;
        cudaLaunchAttribute attr;
        attr.id = cudaLaunchAttributeProgrammaticStreamSerialization;
        attr.val.programmaticStreamSerializationAllowed = 1;
        cfg.attrs = &attr;
        cfg.numAttrs = 1;
        cudaLaunchKernelEx(&cfg, splat_kernel, cam, buf,
                           voxel_feats, density, viewmats, Ks, pc_xyz);

        loss_kernel<<<HW / 1024, 256>>>(cam, buf, gt_sem, cls_w);
    }
    finalize_kernel<<<1, 32>>>((float*)d_out);
}

// round 8
// speedup vs baseline: 2.0523x; 1.1931x over previous
#include <cuda_runtime.h>
#include <cuda_fp16.h>
#include <math.h>
#include <string.h>

#define H_    512
#define W_    1408
#define HW    (H_ * W_)        // 720896 = 704 * 1024
#define NPTS  640000
#define NCAM  6
#define NCH   17

// Scratch (allocation-free rule: __device__ globals).
// Ping-pong buffers. Main image: 16 channels/pixel fp16 = 32B/pixel (23MB).
// Channel 16 lives in a separate planar half array (1.4MB).
// Invariant: zero at entry of every kernel_launch; loss(c) re-zeroes the
// buffer it reads; next user of that buffer is 2 kernels downstream.
__device__ __align__(256) __half g16[2][(size_t)HW * 16];
__device__ __align__(256) __half g1[2][(size_t)HW + 8];   // +8 pad for merged tail write
__device__ float g_num[NCAM];
__device__ float g_den[NCAM];

__device__ __forceinline__ unsigned h2_bits(__half2 h) {
    unsigned u;
    memcpy(&u, &h, 4);
    return u;
}

__device__ __forceinline__ void red_add_v4_h2(__half* addr, unsigned a, unsigned b,
                                              unsigned c, unsigned d) {
    asm volatile("red.global.add.noftz.v4.f16x2 [%0], {%1, %2, %3, %4};"
                 :: "l"(addr), "r"(a), "r"(b), "r"(c), "r"(d)
                 : "memory");
}
__device__ __forceinline__ void red_add_h2(__half* addr, __half2 v) {
    asm volatile("red.global.add.noftz.f16x2 [%0], %1;"
                 :: "l"(addr), "r"(h2_bits(v))
                 : "memory");
}
__device__ __forceinline__ void red_add_h(__half* addr, __half v) {
    unsigned short s;
    memcpy(&s, &v, 2);
    asm volatile("red.global.add.noftz.f16 [%0], %1;"
                 :: "l"(addr), "h"(s)
                 : "memory");
}

__global__ __launch_bounds__(256)
void splat_kernel(int cam, int buf,
                  const float* __restrict__ feats,
                  const float* __restrict__ density,
                  const float* __restrict__ viewmats,
                  const float* __restrict__ Ks,
                  const float* __restrict__ xyz)
{
    int p = blockIdx.x * 256 + threadIdx.x;
    if (p >= NPTS) return;

    float X = __ldcs(xyz + 3 * p + 0);
    float Y = __ldcs(xyz + 3 * p + 1);
    float Z = __ldcs(xyz + 3 * p + 2);

    const float* V = viewmats + cam * 16;
    const float* K = Ks + cam * 9;

    float px = V[0] * X + V[1] * Y + V[2]  * Z + V[3];
    float py = V[4] * X + V[5] * Y + V[6]  * Z + V[7];
    float pz = V[8] * X + V[9] * Y + V[10] * Z + V[11];

    // reference: valid requires p.z > 0.1 (else all 9 taps contribute 0)
    if (!(pz > 0.1f)) return;

    float z  = fmaxf(pz, 0.001f);
    float fx = K[0], cx = K[2], fy = K[4], cy = K[5];

    float u = fx * px / z + cx;
    float v = fy * py / z + cy;

    const float s2 = 0.4f * 0.4f;
    float j00 = fx / z;
    float j11 = fy / z;
    float j02 = -fx * px / (z * z);
    float j12 = -fy * py / (z * z);

    float a = s2 * (j00 * j00 + j02 * j02) + 0.3f;
    float b = s2 * (j02 * j12);
    float c = s2 * (j11 * j11 + j12 * j12) + 0.3f;
    float det = a * c - b * b;
    float ca =  c / det;
    float cb = -b / det;
    float cc =  a / det;

    float ru = rintf(u);   // matches jnp.round (half-to-even)
    float rv = rintf(v);

    // quick full-footprint reject (all 9 taps out of image)
    if (ru < -1.0f || ru > (float)W_ || rv < -1.0f || rv > (float)H_) return;

    float opac = __ldcs(density + p);

    // Pack the 17-ch feature vector into half2 registers (pad with 0).
    __half2 fh[8];
    __half  f16h;
    {
        float f[NCH];
#pragma unroll
        for (int ch = 0; ch < NCH; ch++) f[ch] = __ldcs(feats + (size_t)p * NCH + ch);
#pragma unroll
        for (int i = 0; i < 8; i++) fh[i] = __floats2half2_rn(f[2 * i], f[2 * i + 1]);
        f16h = __float2half_rn(f[16]);
    }

    __half* img16 = g16[buf];
    __half* img1  = g1[buf];

    int   iu      = (int)ru;
    bool  u_inner = (ru >= 1.0f) && (ru <= (float)(W_ - 2));  // all 3 dx taps in-bounds

#pragma unroll
    for (int r = 0; r < 3; r++) {
        float pyy = rv + (float)(r - 1);
        if (pyy < 0.0f || pyy >= (float)H_) continue;
        float ddy = pyy - v;
        int   rowbase = (int)pyy * W_ + iu - 1;   // pixel index of dx=-1 tap

        if (u_inner) {
            __half c16[3];
#pragma unroll
            for (int t = 0; t < 3; t++) {
                float ddx = (ru + (float)(t - 1)) - u;
                float e = -0.5f * (ca * ddx * ddx + 2.0f * cb * ddx * ddy + cc * ddy * ddy);
                float w = opac * __expf(e);
                __half2 wh = __float2half2_rn(w);

                __half* bp = img16 + (size_t)(rowbase + t) * 16;
                red_add_v4_h2(bp + 0, h2_bits(__hmul2(wh, fh[0])), h2_bits(__hmul2(wh, fh[1])),
                                      h2_bits(__hmul2(wh, fh[2])), h2_bits(__hmul2(wh, fh[3])));
                red_add_v4_h2(bp + 8, h2_bits(__hmul2(wh, fh[4])), h2_bits(__hmul2(wh, fh[5])),
                                      h2_bits(__hmul2(wh, fh[6])), h2_bits(__hmul2(wh, fh[7])));
                c16[t] = __hmul(__low2half(wh), f16h);
            }
            // merged ch16: 3 contiguous halves -> two 4B-aligned f16x2 REDs (+0 padding)
            const __half hz = __ushort_as_half((unsigned short)0);
            int  e2  = rowbase & ~1;
            bool odd = (rowbase & 1) != 0;
            __half2 h2a = odd ? __halves2half2(hz, c16[0]) : __halves2half2(c16[0], c16[1]);
            __half2 h2b = odd ? __halves2half2(c16[1], c16[2]) : __halves2half2(c16[2], hz);
            red_add_h2(img1 + e2,     h2a);
            red_add_h2(img1 + e2 + 2, h2b);
        } else {
            // border fallback: per-tap guarded (matches reference exactly)
#pragma unroll
            for (int t = 0; t < 3; t++) {
                float pxx = ru + (float)(t - 1);
                if (pxx < 0.0f || pxx >= (float)W_) continue;
                float ddx = pxx - u;
                float e = -0.5f * (ca * ddx * ddx + 2.0f * cb * ddx * ddy + cc * ddy * ddy);
                float w = opac * __expf(e);
                __half2 wh = __float2half2_rn(w);
                int pix = rowbase + t;
                __half* bp = img16 + (size_t)pix * 16;
                red_add_v4_h2(bp + 0, h2_bits(__hmul2(wh, fh[0])), h2_bits(__hmul2(wh, fh[1])),
                                      h2_bits(__hmul2(wh, fh[2])), h2_bits(__hmul2(wh, fh[3])));
                red_add_v4_h2(bp + 8, h2_bits(__hmul2(wh, fh[4])), h2_bits(__hmul2(wh, fh[5])),
                                      h2_bits(__hmul2(wh, fh[6])), h2_bits(__hmul2(wh, fh[7])));
                red_add_h(img1 + pix, __hmul(__low2half(wh), f16h));
            }
        }
    }
}

// Single-wave-ish loss: 352 blocks x 256 threads x 8 pixels (MLP-heavy).
// Triggers PDL completion at entry so the next splat (other buffer) overlaps.
__global__ __launch_bounds__(256)
void loss_kernel(int cam, int buf, const int* __restrict__ gt, const float* __restrict__ cw)
{
#if __CUDA_ARCH__ >= 900
    cudaTriggerProgrammaticLaunchCompletion();
#endif

    float nwl = 0.0f, wv = 0.0f;
    __half* img16 = g16[buf];
    __half* img1  = g1[buf];

#pragma unroll
    for (int j = 0; j < 8; j++) {
        int pix = blockIdx.x * 2048 + j * 256 + threadIdx.x;
        __half* bp = img16 + (size_t)pix * 16;

        uint4 q0 = ((const uint4*)bp)[0];   // halves 0..7
        uint4 q1 = ((const uint4*)bp)[1];   // halves 8..15
        __half h16 = img1[pix];

        float l[NCH];
        {
            float2 t;
            t = __half22float2(*(__half2*)&q0.x); l[0] = t.x;  l[1] = t.y;
            t = __half22float2(*(__half2*)&q0.y); l[2] = t.x;  l[3] = t.y;
            t = __half22float2(*(__half2*)&q0.z); l[4] = t.x;  l[5] = t.y;
            t = __half22float2(*(__half2*)&q0.w); l[6] = t.x;  l[7] = t.y;
            t = __half22float2(*(__half2*)&q1.x); l[8] = t.x;  l[9] = t.y;
            t = __half22float2(*(__half2*)&q1.y); l[10] = t.x; l[11] = t.y;
            t = __half22float2(*(__half2*)&q1.z); l[12] = t.x; l[13] = t.y;
            t = __half22float2(*(__half2*)&q1.w); l[14] = t.x; l[15] = t.y;
            l[16] = __half2float(h16);
        }

        float m = l[0];
#pragma unroll
        for (int ch = 1; ch < NCH; ch++) m = fmaxf(m, l[ch]);
        float s = 0.0f;
#pragma unroll
        for (int ch = 0; ch < NCH; ch++) s += __expf(l[ch] - m);
        float lse = m + __logf(s);

        int g = __ldcs(gt + (size_t)cam * HW + pix);  // in [0,17)
        float lg = (g < 16) ? __half2float(bp[g]) : l[16];
        float w = (g != 0) ? cw[g] : 0.0f;

        nwl += w * (lse - lg);
        wv  += w;

        // restore invariant: zero the image before this buffer's next splat
        uint4 z4 = make_uint4(0u, 0u, 0u, 0u);
        ((uint4*)bp)[0] = z4;
        ((uint4*)bp)[1] = z4;
        img1[pix] = __ushort_as_half((unsigned short)0);
    }

    // block reduction
#pragma unroll
    for (int o = 16; o > 0; o >>= 1) {
        nwl += __shfl_down_sync(0xffffffffu, nwl, o);
        wv  += __shfl_down_sync(0xffffffffu, wv,  o);
    }
    __shared__ float sh[16];
    int lane = threadIdx.x & 31;
    int wid  = threadIdx.x >> 5;
    if (lane == 0) { sh[wid] = nwl; sh[8 + wid] = wv; }
    __syncthreads();
    if (threadIdx.x == 0) {
        float an = 0.0f, ad = 0.0f;
#pragma unroll
        for (int i = 0; i < 8; i++) { an += sh[i]; ad += sh[8 + i]; }
        atomicAdd(&g_num[cam], an);
        atomicAdd(&g_den[cam], ad);
    }
}

__global__ void finalize_kernel(float* out)
{
    if (threadIdx.x == 0 && blockIdx.x == 0) {
        float L = 0.0f;
#pragma unroll
        for (int cam = 0; cam < NCAM; cam++) {
            L += g_num[cam] / fmaxf(g_den[cam], 1e-8f);
            g_num[cam] = 0.0f;   // reset accumulators for next replay
            g_den[cam] = 0.0f;
        }
        out[0] = L / (float)NCAM;
    }
}

extern "C" void kernel_launch(void* const* d_in, const int* in_sizes, int n_in,
                              void* d_out, int out_size)
{
    const float* voxel_feats = (const float*)d_in[0];
    const float* density     = (const float*)d_in[1];
    const float* viewmats    = (const float*)d_in[2];
    const float* Ks          = (const float*)d_in[3];
    const int*   gt_sem      = (const int*)d_in[4];
    const float* pc_xyz      = (const float*)d_in[5];
    const float* cls_w       = (const float*)d_in[6];

    for (int cam = 0; cam < NCAM; cam++) {
        int buf = cam & 1;

        // splat with PDL: may start while the previous loss (other buffer) runs
        cudaLaunchConfig_t cfg = {};
        cfg.gridDim  = dim3((NPTS + 255) / 256);
        cfg.blockDim = dim3(256);
        cfg.stream   = 0;
        cudaLaunchAttribute attr;
        attr.id = cudaLaunchAttributeProgrammaticStreamSerialization;
        attr.val.programmaticStreamSerializationAllowed = 1;
        cfg.attrs = &attr;
        cfg.numAttrs = 1;
        cudaLaunchKernelEx(&cfg, splat_kernel, cam, buf,
                           voxel_feats, density, viewmats, Ks, pc_xyz);

        loss_kernel<<<HW / 2048, 256>>>(cam, buf, gt_sem, cls_w);
    }
    finalize_kernel<<<1, 32>>>((float*)d_out);
}